// round 8
// baseline (speedup 1.0000x reference)
#include <cuda_runtime.h>
#include <math.h>

// ZINBDecoder R8: converged LDG.64 rows + f32x2 math + 8-edge fold,
// gef/szf staged in shared memory (48KB) with a bounded grid so staging
// amortizes over ~1700 edges/block. Leader scalar reads become LDS,
// removing ~2 L1 lines/edge from the binding L1-wavefront budget.
// out = [mu | disp | pi], fp32.

typedef unsigned long long u64;

#define N_GENES 2000
#define N_CELLS 10000

__device__ __forceinline__ u64 fmul2(u64 a, u64 b) {
    u64 d;
    asm("mul.rn.f32x2 %0, %1, %2;" : "=l"(d) : "l"(a), "l"(b));
    return d;
}

__device__ __forceinline__ u64 ffma2(u64 a, u64 b, u64 c) {
    u64 d;
    asm("fma.rn.f32x2 %0, %1, %2, %3;" : "=l"(d) : "l"(a), "l"(b), "l"(c));
    return d;
}

__device__ __forceinline__ float unpack_sum(u64 p) {
    unsigned int lo, hi;
    asm("mov.b64 {%0, %1}, %2;" : "=r"(lo), "=r"(hi) : "l"(p));
    return __uint_as_float(lo) + __uint_as_float(hi);
}

__device__ __forceinline__ float fast_sigmoid(float x) {
    return __fdividef(1.0f, 1.0f + __expf(-x));
}

__global__ void __launch_bounds__(256)
zinb_kernel(const float* __restrict__ ufeats,
            const float* __restrict__ ifeats,
            const float* __restrict__ ge_factor,
            const float* __restrict__ sz_factor,
            const float* __restrict__ W_mean,
            const float* __restrict__ b_mean,
            const float* __restrict__ W_disp,
            const float* __restrict__ b_disp,
            const float* __restrict__ W_pi,
            const float* __restrict__ b_pi,
            const int*   __restrict__ src_idx,
            const int*   __restrict__ dst_idx,
            float* __restrict__ out,
            long long block_edges,
            int E)
{
    __shared__ float s_gef[N_GENES];
    __shared__ float s_szf[N_CELLS];

    const int tid  = threadIdx.x;
    const int lane = tid & 31;

    // ---- Stage factor tables into smem (float4, coalesced).
    {
        const float4* __restrict__ g4 = reinterpret_cast<const float4*>(ge_factor);
        const float4* __restrict__ z4 = reinterpret_cast<const float4*>(sz_factor);
        float4* __restrict__ sg4 = reinterpret_cast<float4*>(s_gef);
        float4* __restrict__ sz4 = reinterpret_cast<float4*>(s_szf);
#pragma unroll
        for (int i = tid; i < N_GENES / 4; i += 256) sg4[i] = g4[i];
#pragma unroll
        for (int i = tid; i < N_CELLS / 4; i += 256) sz4[i] = z4[i];
    }

    const float bm = b_mean[0];
    const float bd = b_disp[0];
    const float bp = b_pi[0];

    // Packed weight pairs in registers: pair (lane) and (lane+32).
    const u64* __restrict__ wm64 = reinterpret_cast<const u64*>(W_mean);
    const u64* __restrict__ wd64 = reinterpret_cast<const u64*>(W_disp);
    const u64* __restrict__ wp64 = reinterpret_cast<const u64*>(W_pi);
    const u64 wm0 = wm64[lane], wm1 = wm64[lane + 32];
    const u64 wd0 = wd64[lane], wd1 = wd64[lane + 32];
    const u64 wp0 = wp64[lane], wp1 = wp64[lane + 32];

    __syncthreads();

    // Contiguous edge range for this block; warps take 8-edge groups,
    // striding by 64 (8 warps) within the range.
    const long long blk_lo = (long long)blockIdx.x * block_edges;
    const long long blk_hi = min(blk_lo + block_edges, (long long)E);
    const int       wid    = tid >> 5;

#pragma unroll 1
    for (long long base = blk_lo + (long long)wid * 8; base < blk_hi; base += 64) {

        // Lanes 0..7 (replicated 4x) hold the 8 edges' indices.
        const int       jl   = lane & 7;
        const long long e_l  = base + jl;
        const int       e_lc = (e_l < E) ? (int)e_l : (E - 1);
        const int s_l = src_idx[e_lc];
        const int g_l = dst_idx[e_lc];

        float val[24];

        // Whole warp processes edge j: 2x LDG.64 per 512B row, coalesced.
#pragma unroll
        for (int j = 0; j < 8; ++j) {
            const int s_j = __shfl_sync(0xFFFFFFFFu, s_l, j);
            const int g_j = __shfl_sync(0xFFFFFFFFu, g_l, j);

            const u64* __restrict__ up =
                reinterpret_cast<const u64*>(ufeats + (size_t)s_j * 128);
            const u64* __restrict__ vp =
                reinterpret_cast<const u64*>(ifeats + (size_t)g_j * 128);

            const u64 u0 = up[lane], u1 = up[lane + 32];
            const u64 v0 = vp[lane], v1 = vp[lane + 32];

            const u64 h0 = fmul2(u0, v0);
            const u64 h1 = fmul2(u1, v1);

            u64 am = fmul2(h0, wm0); am = ffma2(h1, wm1, am);
            u64 ad = fmul2(h0, wd0); ad = ffma2(h1, wd1, ad);
            u64 ap = fmul2(h0, wp0); ap = ffma2(h1, wp1, ap);

            val[3*j+0] = unpack_sum(am);
            val[3*j+1] = unpack_sum(ad);
            val[3*j+2] = unpack_sum(ap);
        }

        // ---- Fold 24 -> 12 (xor 16): edge bit2 := lane bit4.
#pragma unroll
        for (int i = 0; i < 12; ++i) {
            const bool  hi   = (lane & 16) != 0;
            const float send = hi ? val[i]      : val[i + 12];
            const float keep = hi ? val[i + 12] : val[i];
            val[i] = keep + __shfl_xor_sync(0xFFFFFFFFu, send, 16);
        }
        // ---- 12 -> 6 (xor 8): edge bit1 := lane bit3.
#pragma unroll
        for (int i = 0; i < 6; ++i) {
            const bool  hi   = (lane & 8) != 0;
            const float send = hi ? val[i]     : val[i + 6];
            const float keep = hi ? val[i + 6] : val[i];
            val[i] = keep + __shfl_xor_sync(0xFFFFFFFFu, send, 8);
        }
        // ---- 6 -> 3 (xor 4): edge bit0 := lane bit2. Quad q owns edge q.
#pragma unroll
        for (int i = 0; i < 3; ++i) {
            const bool  hi   = (lane & 4) != 0;
            const float send = hi ? val[i]     : val[i + 3];
            const float keep = hi ? val[i + 3] : val[i];
            val[i] = keep + __shfl_xor_sync(0xFFFFFFFFu, send, 4);
        }
        // ---- Butterfly within each quad (xor 2, 1).
#pragma unroll
        for (int off = 2; off >= 1; off >>= 1) {
            val[0] += __shfl_xor_sync(0xFFFFFFFFu, val[0], off);
            val[1] += __shfl_xor_sync(0xFFFFFFFFu, val[1], off);
            val[2] += __shfl_xor_sync(0xFFFFFFFFu, val[2], off);
        }

        // Leaders (lanes 0,4,...,28) handle edge (lane>>2).
        const int o   = lane >> 2;
        const int s_o = __shfl_sync(0xFFFFFFFFu, s_l, o);
        const int g_o = __shfl_sync(0xFFFFFFFFu, g_l, o);

        if ((lane & 3) == 0) {
            const long long e_ll = base + o;
            if (e_ll < E) {
                const int e = (int)e_ll;

                const float gef = s_gef[g_o];   // LDS, not L1 lines
                const float szf = s_szf[s_o];

                const float mu_sig = fast_sigmoid(val[0] + bm);
                const float pi_v   = fast_sigmoid(val[2] + bp);

                // stable softplus: max(x,0) + log(1 + exp(-|x|))
                const float x = gef * (val[1] + bd);
                float disp = fmaxf(x, 0.0f) + __logf(1.0f + __expf(-fabsf(x)));
                disp = fminf(fmaxf(disp, 1e-4f), 1e4f);

                float mu = __expf(gef * mu_sig) - 1.0f;   // arg in [0,1]
                mu = fminf(fmaxf(mu, 1e-5f), 1e6f);
                mu *= szf;

                out[e]                 = mu;
                out[(size_t)E + e]     = disp;
                out[(size_t)2 * E + e] = pi_v;
            }
        }
    }
}

extern "C" void kernel_launch(void* const* d_in, const int* in_sizes, int n_in,
                              void* d_out, int out_size)
{
    const float* ufeats    = (const float*)d_in[0];
    const float* ifeats    = (const float*)d_in[1];
    const float* ge_factor = (const float*)d_in[2];
    const float* sz_factor = (const float*)d_in[3];
    const float* W_mean    = (const float*)d_in[4];
    const float* b_mean    = (const float*)d_in[5];
    const float* W_disp    = (const float*)d_in[6];
    const float* b_disp    = (const float*)d_in[7];
    const float* W_pi      = (const float*)d_in[8];
    const float* b_pi      = (const float*)d_in[9];
    const int*   src_idx   = (const int*)d_in[10];
    const int*   dst_idx   = (const int*)d_in[11];
    float* out = (float*)d_out;
    (void)n_in; (void)out_size;

    const int E = in_sizes[10];

    // Bounded grid: 1184 blocks (4/SM target @ 48KB smem). Each block owns a
    // contiguous edge chunk; table staging (48KB/block) amortizes over it.
    const int threads = 256;
    int blocks = 148 * 8;
    // Each block needs >= 64 edges to keep all 8 warps busy once.
    long long max_blocks = ((long long)E + 63) / 64;
    if ((long long)blocks > max_blocks) blocks = (int)max_blocks;
    // Round block_edges to a multiple of 64 (warp group granularity).
    long long block_edges = ((long long)E + blocks - 1) / blocks;
    block_edges = ((block_edges + 63) / 64) * 64;
    blocks = (int)(((long long)E + block_edges - 1) / block_edges);

    zinb_kernel<<<blocks, threads>>>(
        ufeats, ifeats, ge_factor, sz_factor,
        W_mean, b_mean, W_disp, b_disp, W_pi, b_pi,
        src_idx, dst_idx, out, block_edges, E);
}

// round 9
// speedup vs baseline: 1.7484x; 1.7484x over previous
#include <cuda_runtime.h>
#include <math.h>

// ZINBDecoder R9: R7 core (converged LDG.64 rows + f32x2 + 8-edge fold)
// + gef/szf tables staged in 48KB smem, amortized over 1024-edge blocks,
// with registers capped at 64 and all-int indexing to preserve 4 blocks/SM.
// out = [mu | disp | pi], fp32.

typedef unsigned long long u64;

#define N_GENES 2000
#define N_CELLS 10000
#define ITERS   16           // 8 edges/iter -> 128 edges per warp
#define EDGES_PER_BLOCK 1024 // 8 warps * 128

__device__ __forceinline__ u64 fmul2(u64 a, u64 b) {
    u64 d;
    asm("mul.rn.f32x2 %0, %1, %2;" : "=l"(d) : "l"(a), "l"(b));
    return d;
}

__device__ __forceinline__ u64 ffma2(u64 a, u64 b, u64 c) {
    u64 d;
    asm("fma.rn.f32x2 %0, %1, %2, %3;" : "=l"(d) : "l"(a), "l"(b), "l"(c));
    return d;
}

__device__ __forceinline__ float unpack_sum(u64 p) {
    unsigned int lo, hi;
    asm("mov.b64 {%0, %1}, %2;" : "=r"(lo), "=r"(hi) : "l"(p));
    return __uint_as_float(lo) + __uint_as_float(hi);
}

__device__ __forceinline__ float fast_sigmoid(float x) {
    return __fdividef(1.0f, 1.0f + __expf(-x));
}

__global__ void __launch_bounds__(256, 4)
zinb_kernel(const float* __restrict__ ufeats,
            const float* __restrict__ ifeats,
            const float* __restrict__ ge_factor,
            const float* __restrict__ sz_factor,
            const float* __restrict__ W_mean,
            const float* __restrict__ b_mean,
            const float* __restrict__ W_disp,
            const float* __restrict__ b_disp,
            const float* __restrict__ W_pi,
            const float* __restrict__ b_pi,
            const int*   __restrict__ src_idx,
            const int*   __restrict__ dst_idx,
            float* __restrict__ out,
            int E)
{
    __shared__ float s_gef[N_GENES];
    __shared__ float s_szf[N_CELLS];

    const int tid  = threadIdx.x;
    const int lane = tid & 31;

    // ---- Stage factor tables into smem (float4, coalesced).
    {
        const float4* __restrict__ g4 = reinterpret_cast<const float4*>(ge_factor);
        const float4* __restrict__ z4 = reinterpret_cast<const float4*>(sz_factor);
        float4* __restrict__ sg4 = reinterpret_cast<float4*>(s_gef);
        float4* __restrict__ sz4 = reinterpret_cast<float4*>(s_szf);
        for (int i = tid; i < N_GENES / 4; i += 256) sg4[i] = g4[i];
        for (int i = tid; i < N_CELLS / 4; i += 256) sz4[i] = z4[i];
    }

    const float bm = b_mean[0];
    const float bd = b_disp[0];
    const float bp = b_pi[0];

    // Packed weight pairs in registers: pair (lane) and (lane+32).
    const u64* __restrict__ wm64 = reinterpret_cast<const u64*>(W_mean);
    const u64* __restrict__ wd64 = reinterpret_cast<const u64*>(W_disp);
    const u64* __restrict__ wp64 = reinterpret_cast<const u64*>(W_pi);
    const u64 wm0 = wm64[lane], wm1 = wm64[lane + 32];
    const u64 wd0 = wd64[lane], wd1 = wd64[lane + 32];
    const u64 wp0 = wp64[lane], wp1 = wp64[lane + 32];

    __syncthreads();

    // Contiguous 1024-edge chunk per block; warp w owns 128 of them.
    const int wid   = tid >> 5;
    const int base0 = blockIdx.x * EDGES_PER_BLOCK + wid * (8 * ITERS);

#pragma unroll 1
    for (int it = 0; it < ITERS; ++it) {
        const int base = base0 + it * 8;
        if (base >= E) break;

        // Lanes 0..7 (replicated 4x) hold the 8 edges' indices.
        const int jl   = lane & 7;
        const int e_l0 = base + jl;
        const int e_lc = (e_l0 < E) ? e_l0 : (E - 1);
        const int s_l  = src_idx[e_lc];
        const int g_l  = dst_idx[e_lc];

        float val[24];

        // Whole warp processes edge j: 2x LDG.64 per 512B row, coalesced.
#pragma unroll
        for (int j = 0; j < 8; ++j) {
            const int s_j = __shfl_sync(0xFFFFFFFFu, s_l, j);
            const int g_j = __shfl_sync(0xFFFFFFFFu, g_l, j);

            const u64* __restrict__ up =
                reinterpret_cast<const u64*>(ufeats + (size_t)s_j * 128);
            const u64* __restrict__ vp =
                reinterpret_cast<const u64*>(ifeats + (size_t)g_j * 128);

            const u64 u0 = up[lane], u1 = up[lane + 32];
            const u64 v0 = vp[lane], v1 = vp[lane + 32];

            const u64 h0 = fmul2(u0, v0);
            const u64 h1 = fmul2(u1, v1);

            u64 am = fmul2(h0, wm0); am = ffma2(h1, wm1, am);
            u64 ad = fmul2(h0, wd0); ad = ffma2(h1, wd1, ad);
            u64 ap = fmul2(h0, wp0); ap = ffma2(h1, wp1, ap);

            val[3*j+0] = unpack_sum(am);
            val[3*j+1] = unpack_sum(ad);
            val[3*j+2] = unpack_sum(ap);
        }

        // ---- Fold 24 -> 12 (xor 16): edge bit2 := lane bit4.
#pragma unroll
        for (int i = 0; i < 12; ++i) {
            const bool  hi   = (lane & 16) != 0;
            const float send = hi ? val[i]      : val[i + 12];
            const float keep = hi ? val[i + 12] : val[i];
            val[i] = keep + __shfl_xor_sync(0xFFFFFFFFu, send, 16);
        }
        // ---- 12 -> 6 (xor 8): edge bit1 := lane bit3.
#pragma unroll
        for (int i = 0; i < 6; ++i) {
            const bool  hi   = (lane & 8) != 0;
            const float send = hi ? val[i]     : val[i + 6];
            const float keep = hi ? val[i + 6] : val[i];
            val[i] = keep + __shfl_xor_sync(0xFFFFFFFFu, send, 8);
        }
        // ---- 6 -> 3 (xor 4): edge bit0 := lane bit2. Quad q owns edge q.
#pragma unroll
        for (int i = 0; i < 3; ++i) {
            const bool  hi   = (lane & 4) != 0;
            const float send = hi ? val[i]     : val[i + 3];
            const float keep = hi ? val[i + 3] : val[i];
            val[i] = keep + __shfl_xor_sync(0xFFFFFFFFu, send, 4);
        }
        // ---- Butterfly within each quad (xor 2, 1).
#pragma unroll
        for (int off = 2; off >= 1; off >>= 1) {
            val[0] += __shfl_xor_sync(0xFFFFFFFFu, val[0], off);
            val[1] += __shfl_xor_sync(0xFFFFFFFFu, val[1], off);
            val[2] += __shfl_xor_sync(0xFFFFFFFFu, val[2], off);
        }

        // Leaders (lanes 0,4,...,28) handle edge (lane>>2).
        const int o   = lane >> 2;
        const int s_o = __shfl_sync(0xFFFFFFFFu, s_l, o);
        const int g_o = __shfl_sync(0xFFFFFFFFu, g_l, o);

        if ((lane & 3) == 0) {
            const int e = base + o;
            if (e < E) {
                const float gef = s_gef[g_o];   // LDS, not L1 lines
                const float szf = s_szf[s_o];

                const float mu_sig = fast_sigmoid(val[0] + bm);
                const float pi_v   = fast_sigmoid(val[2] + bp);

                // stable softplus: max(x,0) + log(1 + exp(-|x|))
                const float x = gef * (val[1] + bd);
                float disp = fmaxf(x, 0.0f) + __logf(1.0f + __expf(-fabsf(x)));
                disp = fminf(fmaxf(disp, 1e-4f), 1e4f);

                float mu = __expf(gef * mu_sig) - 1.0f;   // arg in [0,1]
                mu = fminf(fmaxf(mu, 1e-5f), 1e6f);
                mu *= szf;

                out[e]                 = mu;
                out[(size_t)E + e]     = disp;
                out[(size_t)2 * E + e] = pi_v;
            }
        }
    }
}

extern "C" void kernel_launch(void* const* d_in, const int* in_sizes, int n_in,
                              void* d_out, int out_size)
{
    const float* ufeats    = (const float*)d_in[0];
    const float* ifeats    = (const float*)d_in[1];
    const float* ge_factor = (const float*)d_in[2];
    const float* sz_factor = (const float*)d_in[3];
    const float* W_mean    = (const float*)d_in[4];
    const float* b_mean    = (const float*)d_in[5];
    const float* W_disp    = (const float*)d_in[6];
    const float* b_disp    = (const float*)d_in[7];
    const float* W_pi      = (const float*)d_in[8];
    const float* b_pi      = (const float*)d_in[9];
    const int*   src_idx   = (const int*)d_in[10];
    const int*   dst_idx   = (const int*)d_in[11];
    float* out = (float*)d_out;
    (void)n_in; (void)out_size;

    const int E = in_sizes[10];

    const int threads = 256;
    const int blocks  = (E + EDGES_PER_BLOCK - 1) / EDGES_PER_BLOCK;

    zinb_kernel<<<blocks, threads>>>(
        ufeats, ifeats, ge_factor, sz_factor,
        W_mean, b_mean, W_disp, b_disp, W_pi, b_pi,
        src_idx, dst_idx, out, E);
}

// round 10
// speedup vs baseline: 1.9504x; 1.1156x over previous
#include <cuda_runtime.h>
#include <math.h>

// ZINBDecoder R10: R7 core (converged LDG.64 rows + f32x2 + 8-edge fold),
// restructured for occupancy:
//   - progressive xor16 fold (peak live partials 12+6, not 24)
//   - index prefetch for the next 8-edge group
//   - biases loaded only in the leader epilogue
//   - __launch_bounds__(256, 5): 51-reg cap -> 5 blocks/SM = 40 warps
// out = [mu | disp | pi], fp32.

typedef unsigned long long u64;

#define ITERS 4   // 8 edges/iter -> 32 edges per warp

__device__ __forceinline__ u64 fmul2(u64 a, u64 b) {
    u64 d;
    asm("mul.rn.f32x2 %0, %1, %2;" : "=l"(d) : "l"(a), "l"(b));
    return d;
}

__device__ __forceinline__ u64 ffma2(u64 a, u64 b, u64 c) {
    u64 d;
    asm("fma.rn.f32x2 %0, %1, %2, %3;" : "=l"(d) : "l"(a), "l"(b), "l"(c));
    return d;
}

__device__ __forceinline__ float unpack_sum(u64 p) {
    unsigned int lo, hi;
    asm("mov.b64 {%0, %1}, %2;" : "=r"(lo), "=r"(hi) : "l"(p));
    return __uint_as_float(lo) + __uint_as_float(hi);
}

__device__ __forceinline__ float fast_sigmoid(float x) {
    return __fdividef(1.0f, 1.0f + __expf(-x));
}

__global__ void __launch_bounds__(256, 5)
zinb_kernel(const float* __restrict__ ufeats,
            const float* __restrict__ ifeats,
            const float* __restrict__ ge_factor,
            const float* __restrict__ sz_factor,
            const float* __restrict__ W_mean,
            const float* __restrict__ b_mean,
            const float* __restrict__ W_disp,
            const float* __restrict__ b_disp,
            const float* __restrict__ W_pi,
            const float* __restrict__ b_pi,
            const int*   __restrict__ src_idx,
            const int*   __restrict__ dst_idx,
            float* __restrict__ out,
            int E)
{
    const int tid  = threadIdx.x;
    const int lane = tid & 31;

    // Packed weight pairs in registers: pair (lane) and (lane+32).
    const u64* __restrict__ wm64 = reinterpret_cast<const u64*>(W_mean);
    const u64* __restrict__ wd64 = reinterpret_cast<const u64*>(W_disp);
    const u64* __restrict__ wp64 = reinterpret_cast<const u64*>(W_pi);
    const u64 wm0 = wm64[lane], wm1 = wm64[lane + 32];
    const u64 wd0 = wd64[lane], wd1 = wd64[lane + 32];
    const u64 wp0 = wp64[lane], wp1 = wp64[lane + 32];

    const int gwarp = (blockIdx.x * blockDim.x + tid) >> 5;
    const int base0 = gwarp * (8 * ITERS);   // warp's contiguous 32 edges
    const int jl    = lane & 7;

    // Preload indices for the first 8-edge group.
    int e_pf = base0 + jl;
    int s_l  = src_idx[(e_pf < E) ? e_pf : (E - 1)];
    int g_l  = dst_idx[(e_pf < E) ? e_pf : (E - 1)];

#pragma unroll 1
    for (int it = 0; it < ITERS; ++it) {
        const int base = base0 + it * 8;
        if (base >= E) break;

        const int s_cur = s_l;
        const int g_cur = g_l;

        // Prefetch next group's indices (hides idx load latency).
        if (it + 1 < ITERS) {
            e_pf = base + 8 + jl;
            const int e_c = (e_pf < E) ? e_pf : (E - 1);
            s_l = src_idx[e_c];
            g_l = dst_idx[e_c];
        }

        float f[12];

        // Progressive fold: edges (jp, jp+4) computed then xor16-folded.
#pragma unroll
        for (int jp = 0; jp < 4; ++jp) {
            // ---- edge A = jp
            const int sA = __shfl_sync(0xFFFFFFFFu, s_cur, jp);
            const int gA = __shfl_sync(0xFFFFFFFFu, g_cur, jp);
            const u64* __restrict__ upA =
                reinterpret_cast<const u64*>(ufeats + (size_t)sA * 128);
            const u64* __restrict__ vpA =
                reinterpret_cast<const u64*>(ifeats + (size_t)gA * 128);
            const u64 ha0 = fmul2(upA[lane], vpA[lane]);
            const u64 ha1 = fmul2(upA[lane + 32], vpA[lane + 32]);
            u64 am = fmul2(ha0, wm0); am = ffma2(ha1, wm1, am);
            u64 ad = fmul2(ha0, wd0); ad = ffma2(ha1, wd1, ad);
            u64 ap = fmul2(ha0, wp0); ap = ffma2(ha1, wp1, ap);
            float aA[3];
            aA[0] = unpack_sum(am);
            aA[1] = unpack_sum(ad);
            aA[2] = unpack_sum(ap);

            // ---- edge B = jp + 4
            const int sB = __shfl_sync(0xFFFFFFFFu, s_cur, jp + 4);
            const int gB = __shfl_sync(0xFFFFFFFFu, g_cur, jp + 4);
            const u64* __restrict__ upB =
                reinterpret_cast<const u64*>(ufeats + (size_t)sB * 128);
            const u64* __restrict__ vpB =
                reinterpret_cast<const u64*>(ifeats + (size_t)gB * 128);
            const u64 hb0 = fmul2(upB[lane], vpB[lane]);
            const u64 hb1 = fmul2(upB[lane + 32], vpB[lane + 32]);
            u64 bm_ = fmul2(hb0, wm0); bm_ = ffma2(hb1, wm1, bm_);
            u64 bd_ = fmul2(hb0, wd0); bd_ = ffma2(hb1, wd1, bd_);
            u64 bp_ = fmul2(hb0, wp0); bp_ = ffma2(hb1, wp1, bp_);
            float aB[3];
            aB[0] = unpack_sum(bm_);
            aB[1] = unpack_sum(bd_);
            aB[2] = unpack_sum(bp_);

            // ---- xor16 fold: lanes bit4=0 keep edge jp, bit4=1 keep jp+4.
#pragma unroll
            for (int i = 0; i < 3; ++i) {
                const bool  hi   = (lane & 16) != 0;
                const float send = hi ? aA[i] : aB[i];
                const float keep = hi ? aB[i] : aA[i];
                f[jp * 3 + i] = keep + __shfl_xor_sync(0xFFFFFFFFu, send, 16);
            }
        }

        // ---- 12 -> 6 (xor 8): edge bit1 := lane bit3.
#pragma unroll
        for (int i = 0; i < 6; ++i) {
            const bool  hi   = (lane & 8) != 0;
            const float send = hi ? f[i]     : f[i + 6];
            const float keep = hi ? f[i + 6] : f[i];
            f[i] = keep + __shfl_xor_sync(0xFFFFFFFFu, send, 8);
        }
        // ---- 6 -> 3 (xor 4): edge bit0 := lane bit2. Quad q owns edge q.
#pragma unroll
        for (int i = 0; i < 3; ++i) {
            const bool  hi   = (lane & 4) != 0;
            const float send = hi ? f[i]     : f[i + 3];
            const float keep = hi ? f[i + 3] : f[i];
            f[i] = keep + __shfl_xor_sync(0xFFFFFFFFu, send, 4);
        }
        // ---- Butterfly within each quad (xor 2, 1).
#pragma unroll
        for (int off = 2; off >= 1; off >>= 1) {
            f[0] += __shfl_xor_sync(0xFFFFFFFFu, f[0], off);
            f[1] += __shfl_xor_sync(0xFFFFFFFFu, f[1], off);
            f[2] += __shfl_xor_sync(0xFFFFFFFFu, f[2], off);
        }

        // Leaders (lanes 0,4,...,28) handle edge (lane>>2).
        const int o   = lane >> 2;
        const int s_o = __shfl_sync(0xFFFFFFFFu, s_cur, o);
        const int g_o = __shfl_sync(0xFFFFFFFFu, g_cur, o);

        if ((lane & 3) == 0) {
            const int e = base + o;
            if (e < E) {
                const float gef = ge_factor[g_o];
                const float szf = sz_factor[s_o];

                const float mu_sig = fast_sigmoid(f[0] + b_mean[0]);
                const float pi_v   = fast_sigmoid(f[2] + b_pi[0]);

                // stable softplus: max(x,0) + log(1 + exp(-|x|))
                const float x = gef * (f[1] + b_disp[0]);
                float disp = fmaxf(x, 0.0f) + __logf(1.0f + __expf(-fabsf(x)));
                disp = fminf(fmaxf(disp, 1e-4f), 1e4f);

                float mu = __expf(gef * mu_sig) - 1.0f;   // arg in [0,1]
                mu = fminf(fmaxf(mu, 1e-5f), 1e6f);
                mu *= szf;

                out[e]                 = mu;
                out[(size_t)E + e]     = disp;
                out[(size_t)2 * E + e] = pi_v;
            }
        }
    }
}

extern "C" void kernel_launch(void* const* d_in, const int* in_sizes, int n_in,
                              void* d_out, int out_size)
{
    const float* ufeats    = (const float*)d_in[0];
    const float* ifeats    = (const float*)d_in[1];
    const float* ge_factor = (const float*)d_in[2];
    const float* sz_factor = (const float*)d_in[3];
    const float* W_mean    = (const float*)d_in[4];
    const float* b_mean    = (const float*)d_in[5];
    const float* W_disp    = (const float*)d_in[6];
    const float* b_disp    = (const float*)d_in[7];
    const float* W_pi      = (const float*)d_in[8];
    const float* b_pi      = (const float*)d_in[9];
    const int*   src_idx   = (const int*)d_in[10];
    const int*   dst_idx   = (const int*)d_in[11];
    float* out = (float*)d_out;
    (void)n_in; (void)out_size;

    const int E = in_sizes[10];

    // 32 edges per warp, 8 warps per block -> 256 edges per block.
    const int threads = 256;
    const int edges_per_block = 8 * 8 * ITERS;
    const int blocks = (E + edges_per_block - 1) / edges_per_block;

    zinb_kernel<<<blocks, threads>>>(
        ufeats, ifeats, ge_factor, sz_factor,
        W_mean, b_mean, W_disp, b_disp, W_pi, b_pi,
        src_idx, dst_idx, out, E);
}